// round 2
// baseline (speedup 1.0000x reference)
#include <cuda_runtime.h>
#include <math.h>

#define NR   512
#define NO   64
#define NT   20
#define NS   300
#define NBUF 400
#define WIN  48
#define NCTA 32
#define TPB  512
#define NTH  (NCTA*TPB)
#define KPT  16
#define DT_F 0.0001f
#define UUB  500.0f

__device__ float g_wl[NR*NR];
__device__ float g_rsum[NR];
__device__ float g_rssq[NR];
__device__ float g_dgd[NR];
__device__ float g_invnorm;
__device__ float g_pkw[KPT*NTH];
__device__ int   g_pko[KPT*NTH];
__device__ float g_lmt[NO*NR];
__device__ float g_Mbuf[2][NR];
__device__ float g_EI[NR];
__device__ int   g_count;

__device__ __forceinline__ int ld_acquire_gpu(const int* p) {
    int v;
    asm volatile("ld.global.acquire.gpu.b32 %0, [%1];" : "=r"(v) : "l"(p) : "memory");
    return v;
}
__device__ __forceinline__ void red_release_gpu(int* p, int v) {
    asm volatile("red.release.gpu.global.add.s32 [%0], %1;" :: "l"(p), "r"(v) : "memory");
}

__global__ void k_p1(const float* __restrict__ wbb, const float* __restrict__ sc)
{
    int i = blockIdx.x;
    int t = threadIdx.x;
    float a = expf(wbb[i*NR + t]) * sc[i*NR + t];
    float b = expf(wbb[t*NR + i]) * sc[t*NR + i];
    float wl = log1pf(0.5f * (a + b));
    g_wl[i*NR + t] = wl;

    float s1 = wl, s2 = wl * wl;
    #pragma unroll
    for (int off = 16; off; off >>= 1) {
        s1 += __shfl_down_sync(0xffffffffu, s1, off);
        s2 += __shfl_down_sync(0xffffffffu, s2, off);
    }
    __shared__ float sA[16], sB[16];
    int w = t >> 5, l = t & 31;
    if (l == 0) { sA[w] = s1; sB[w] = s2; }
    __syncthreads();
    if (w == 0) {
        float r1 = (l < 16) ? sA[l] : 0.f;
        float r2 = (l < 16) ? sB[l] : 0.f;
        #pragma unroll
        for (int off = 8; off; off >>= 1) {
            r1 += __shfl_down_sync(0xffffffffu, r1, off);
            r2 += __shfl_down_sync(0xffffffffu, r2, off);
        }
        if (l == 0) { g_rsum[i] = r1; g_rssq[i] = r2; }
    }
}

__global__ void k_p2()
{
    int t = threadIdx.x;
    float s2 = g_rssq[t];
    #pragma unroll
    for (int off = 16; off; off >>= 1) s2 += __shfl_down_sync(0xffffffffu, s2, off);
    __shared__ float sB[16];
    __shared__ float s_inv;
    int w = t >> 5, l = t & 31;
    if (l == 0) sB[w] = s2;
    __syncthreads();
    if (w == 0) {
        float r2 = (l < 16) ? sB[l] : 0.f;
        #pragma unroll
        for (int off = 8; off; off >>= 1) r2 += __shfl_down_sync(0xffffffffu, r2, off);
        if (l == 0) {
            float inv = 1.0f / sqrtf(r2);
            s_inv = inv;
            g_invnorm = inv;
            g_count = 0;
        }
    }
    __syncthreads();
    g_dgd[t] = -s_inv * g_rsum[t];
}

__global__ void k_p3(const float* __restrict__ dist, const float* __restrict__ theta)
{
    int id = blockIdx.x * TPB + threadIdx.x;
    int k   = id >> 14;
    int gt  = id & 16383;
    int c   = gt >> 9;
    int rem = gt & 511;
    int w2  = rem >> 5;
    int l   = rem & 31;
    int i   = c * 16 + w2;
    int j   = l + (k << 5);

    g_pkw[k*NTH + gt] = g_wl[i*NR + j] * g_invnorm;

    float denom = 1.5f + fmaxf(theta[16], 0.0f);
    float q = dist[j*NR + i] / denom;
    int d = (int)q;
    if (d < 0) d = 0;
    if (d > NBUF - 1) d = NBUF - 1;
    if (d > WIN - 1)  d = WIN - 1;
    g_pko[k*NTH + gt] = ((WIN - d) * NR + j) * 4;
}

__global__ void k_p4(const float* __restrict__ lm)
{
    int t = threadIdx.x;
    __shared__ float srs[NO];
    if (t < NO) {
        float s = 0.f;
        for (int i = 0; i < NR; i++) s += fabsf(lm[t*NR + i]);
        srs[t] = s;
    }
    __syncthreads();
    float cm = 0.f;
    for (int o = 0; o < NO; o++) cm += lm[o*NR + t] / srs[o];
    cm *= (1.0f / (float)NO);
    for (int o = 0; o < NO; o++) g_lmt[o*NR + t] = lm[o*NR + t] / srs[o] - cm;
}

__global__ void __launch_bounds__(TPB, 1)
jr_main(const float* __restrict__ theta,
        const float* __restrict__ hx,
        const float* __restrict__ hE0,
        const float* __restrict__ ext,
        const float* __restrict__ noise,
        float* __restrict__ out)
{
    extern __shared__ float sm[];
    float* hist  = sm;                 // [2*WIN][NR]
    float* s_led = sm + 2*WIN*NR;      // [16]

    const int tid = threadIdx.x;
    const int c   = blockIdx.x;
    const int w   = tid >> 5;
    const int l   = tid & 31;
    const int gt  = c * TPB + tid;

    float wk[KPT]; int ok[KPT];
    #pragma unroll
    for (int k = 0; k < KPT; k++) {
        wk[k] = g_pkw[k*NTH + gt];
        ok[k] = g_pko[k*NTH + gt];
    }

    for (int idx = tid; idx < WIN*NR; idx += TPB) {
        int q = idx >> 9;
        int j = idx & 511;
        int cc = (WIN - q) % WIN;
        float v = hE0[j*NBUF + cc];
        hist[q*NR + j]       = v;
        hist[(q+WIN)*NR + j] = v;
    }

    // scalars needed by all warps (EEG) and warp 0 (update)
    const float cy0 = theta[19];
    const float y0_ = theta[15];

    float M=0,E=0,I=0,Mv=0,Ev=0,Iv=0, dgd_i=0;
    float A_=0,a_=0,B_=0,b_=0,gg=0,gf=0,gb=0,c1=0,c2=0,c3=0,c4=0;
    float rstd=0,ncoef=0,vmax=0,v0=0,r_=0,ku=0;
    const int i_reg = c*16 + l;
    if (w == 0) {
        A_ = theta[0];  a_ = theta[1];  B_ = theta[2];  b_ = theta[3];
        gg = 0.01f + fmaxf(theta[4], 0.f);
        gf = 0.01f + fmaxf(theta[5], 0.f);
        gb = 0.01f + fmaxf(theta[6], 0.f);
        c1 = theta[7];  c2 = theta[8];  c3 = theta[9];  c4 = theta[10];
        rstd  = fmaxf(theta[11], 0.f);
        ncoef = 150.f + rstd;
        vmax = theta[12]; v0 = theta[13]; r_ = theta[14];
        ku   = (0.5f + fmaxf(theta[17], 0.f)) * theta[18];
        if (l < 16) {
            M  = hx[i_reg*6 + 0]; E  = hx[i_reg*6 + 1]; I  = hx[i_reg*6 + 2];
            Mv = hx[i_reg*6 + 3]; Ev = hx[i_reg*6 + 4]; Iv = hx[i_reg*6 + 5];
            dgd_i = g_dgd[i_reg];
        }
    }
    __syncthreads();

    int n = 1;
    int pbase = 0;

    for (int wnd = 0; wnd < NT; ++wnd) {
        for (int s = 0; s < NS; ++s) {
            float u_=0, n0=0, n1=0, n2=0;
            if (w == 0 && l < 16) {
                int t_lin = wnd*NS + s;
                const float* nb = noise + (size_t)t_lin * 3 * NR + i_reg;
                n0 = __ldg(nb); n1 = __ldg(nb + NR); n2 = __ldg(nb + 2*NR);
                u_ = __ldg(ext + i_reg*(NS*NT) + s*NT + wnd);
            }

            const char* hrow = (const char*)(hist + pbase);
            float acc0 = 0.f, acc1 = 0.f;
            #pragma unroll
            for (int k = 0; k < KPT; k += 2) {
                acc0 = fmaf(wk[k],   *(const float*)(hrow + ok[k]),   acc0);
                acc1 = fmaf(wk[k+1], *(const float*)(hrow + ok[k+1]), acc1);
            }
            float acc = acc0 + acc1;
            #pragma unroll
            for (int off = 16; off; off >>= 1)
                acc += __shfl_down_sync(0xffffffffu, acc, off);
            if (l == 0) s_led[w] = acc;
            __syncthreads();

            const int par = n & 1;

            if (w == 0) {
                if (l < 16) {
                    float LEd = s_led[l];
                    float EmI = E - I;
                    float S0 = vmax / (1.f + expf(r_ * (v0 - EmI)));
                    float S1 = vmax / (1.f + expf(r_ * (v0 - c1*M)));
                    float S2 = vmax / (1.f + expf(r_ * (v0 - c3*M)));
                    float lmt_ = LEd + dgd_i * M;
                    float let_ = LEd + dgd_i * EmI;
                    float rM = ku*u_ + rstd*n0 + gg*lmt_ + S0;
                    float rE = ncoef*n1 + gf*let_ + c2*S1;
                    float rI = ncoef*n2 - gb*let_ + c4*S2;
                    float Mn = M + DT_F*Mv;
                    float En = E + DT_F*Ev;
                    float In = I + DT_F*Iv;
                    float uM = UUB * tanhf(rM * (1.f/UUB));
                    float uE = UUB * tanhf(rE * (1.f/UUB));
                    float uI = UUB * tanhf(rI * (1.f/UUB));
                    float Mvn = Mv + DT_F*(A_*a_*uM - 2.f*a_*Mv - a_*a_*M);
                    float Evn = Ev + DT_F*(A_*a_*uE - 2.f*a_*Ev - a_*a_*E);
                    float Ivn = Iv + DT_F*(B_*b_*uI - 2.f*b_*Iv - b_*b_*I);
                    M = Mn; E = En; I = In; Mv = Mvn; Ev = Evn; Iv = Ivn;
                    __stcg(&g_Mbuf[par][i_reg], Mn);
                    if (s == NS-1) __stcg(&g_EI[i_reg], En - In);
                }
                __threadfence();
                if (l == 0) {
                    red_release_gpu(&g_count, 1);
                    const int target = NCTA * n;
                    while (ld_acquire_gpu(&g_count) < target) { }
                }
            }
            __syncthreads();

            {
                float v = __ldcg(&g_Mbuf[par][tid]);
                int q = n % WIN;
                hist[q*NR + tid]       = v;
                hist[(q+WIN)*NR + tid] = v;
                pbase = q * NR;
            }

            if (s == NS-1 && (w == 8 || w == 9)) {
                int o = 2*c + (w - 8);
                float sacc = 0.f;
                #pragma unroll
                for (int m = 0; m < 16; m++) {
                    int i2 = l + 32*m;
                    sacc = fmaf(__ldg(&g_lmt[o*NR + i2]), __ldcg(&g_EI[i2]), sacc);
                }
                #pragma unroll
                for (int off = 16; off; off >>= 1)
                    sacc += __shfl_down_sync(0xffffffffu, sacc, off);
                if (l == 0) out[o*NT + wnd] = cy0 * sacc - y0_;
            }

            __syncthreads();
            n++;
        }
    }
}

extern "C" void kernel_launch(void* const* d_in, const int* in_sizes, int n_in,
                              void* d_out, int out_size)
{
    const float* theta = (const float*)d_in[0];
    const float* lm    = (const float*)d_in[1];
    const float* wbb   = (const float*)d_in[2];
    const float* sc    = (const float*)d_in[3];
    const float* dist  = (const float*)d_in[4];
    const float* hx    = (const float*)d_in[5];
    const float* hE0   = (const float*)d_in[6];
    const float* ext   = (const float*)d_in[7];
    const float* noise = (const float*)d_in[8];
    float* out = (float*)d_out;

    (void)in_sizes; (void)n_in; (void)out_size;

    const size_t SMEM = (size_t)(2*WIN*NR + 32) * sizeof(float);
    cudaFuncSetAttribute(jr_main, cudaFuncAttributeMaxDynamicSharedMemorySize, (int)SMEM);

    k_p1<<<NR, TPB>>>(wbb, sc);
    k_p2<<<1, TPB>>>();
    k_p3<<<(KPT*NTH)/TPB, TPB>>>(dist, theta);
    k_p4<<<1, TPB>>>(lm);
    jr_main<<<NCTA, TPB, SMEM>>>(theta, hx, hE0, ext, noise, out);
}